// round 1
// baseline (speedup 1.0000x reference)
#include <cuda_runtime.h>

#define NN 4096
#define FIN 512
#define FO 64
#define NH 8
#define ALPHA 0.2f
#define OUTW (NH * FO)  /* 512 */

// Scratch (static device globals — allocation-free per harness rules)
__device__ float g_Wh[NH * NN * FO];   // 8 MB: [h][n][64]
__device__ float g_el[NH * NN];
__device__ float g_er[NH * NN];
__device__ float g_ermax[NH];

// ---------------------------------------------------------------------------
// Kernel A: Wh[h] = hmat @ W[h] + bW[h]
// grid (NN/64, NH), 128 threads, 64x64 tile, 8x4 per thread, K-tile 16
// ---------------------------------------------------------------------------
__global__ void __launch_bounds__(128) wh_gemm_kernel(
    const float* __restrict__ hmat, const float* __restrict__ W,
    const float* __restrict__ bW)
{
    __shared__ float As[16 * 68];
    __shared__ float Bs[16 * 68];
    const int t  = threadIdx.x;
    const int i0 = blockIdx.x * 64;
    const int hh = blockIdx.y;
    const int rg = t >> 4, cg = t & 15;
    const float* Wp = W + hh * (FIN * FO);

    float acc[8][4];
#pragma unroll
    for (int i = 0; i < 8; i++)
#pragma unroll
        for (int j = 0; j < 4; j++) acc[i][j] = 0.f;

    const int lkk = t & 15;
    const int lr  = t >> 4;

    for (int k0 = 0; k0 < FIN; k0 += 16) {
#pragma unroll
        for (int it = 0; it < 8; it++) {
            int r = lr + 8 * it;
            As[lkk * 68 + r] = hmat[(size_t)(i0 + r) * FIN + k0 + lkk];
        }
#pragma unroll
        for (int it = 0; it < 8; it++) {
            int idx = t + 128 * it;
            int kk = idx >> 6, c = idx & 63;
            Bs[kk * 68 + c] = Wp[(k0 + kk) * FO + c];
        }
        __syncthreads();
#pragma unroll
        for (int kk = 0; kk < 16; kk++) {
            float4 a0 = *(const float4*)(As + kk * 68 + 8 * rg);
            float4 a1 = *(const float4*)(As + kk * 68 + 8 * rg + 4);
            float4 b  = *(const float4*)(Bs + kk * 68 + 4 * cg);
            float ar[8] = {a0.x, a0.y, a0.z, a0.w, a1.x, a1.y, a1.z, a1.w};
            float br[4] = {b.x, b.y, b.z, b.w};
#pragma unroll
            for (int i = 0; i < 8; i++)
#pragma unroll
                for (int j = 0; j < 4; j++)
                    acc[i][j] += ar[i] * br[j];
        }
        __syncthreads();
    }

    float4 bw = *(const float4*)(bW + hh * FO + 4 * cg);
#pragma unroll
    for (int i = 0; i < 8; i++) {
        int r = i0 + 8 * rg + i;
        float4 o;
        o.x = acc[i][0] + bw.x;
        o.y = acc[i][1] + bw.y;
        o.z = acc[i][2] + bw.z;
        o.w = acc[i][3] + bw.w;
        *(float4*)(g_Wh + ((size_t)hh * NN + r) * FO + 4 * cg) = o;
    }
}

// ---------------------------------------------------------------------------
// Kernel B: el[h,n] = Wh[h,n,:].a_l[h] + bA[h] ; er[h,n] = Wh[h,n,:].a_r[h]
// one warp per row, grid = NH*NN/8 blocks of 256
// ---------------------------------------------------------------------------
__global__ void __launch_bounds__(256) eler_kernel(
    const float* __restrict__ a_l, const float* __restrict__ a_r,
    const float* __restrict__ bA)
{
    int row  = blockIdx.x * 8 + (threadIdx.x >> 5);  // over NH*NN
    int lane = threadIdx.x & 31;
    int hh   = row >> 12;  // /NN
    const float* wp = g_Wh + (size_t)row * FO;
    float v0 = wp[lane], v1 = wp[lane + 32];
    float dl = v0 * a_l[hh * FO + lane] + v1 * a_l[hh * FO + lane + 32];
    float dr = v0 * a_r[hh * FO + lane] + v1 * a_r[hh * FO + lane + 32];
#pragma unroll
    for (int off = 16; off > 0; off >>= 1) {
        dl += __shfl_down_sync(0xffffffffu, dl, off);
        dr += __shfl_down_sync(0xffffffffu, dr, off);
    }
    if (lane == 0) {
        g_el[row] = dl + bA[hh];
        g_er[row] = dr;
    }
}

// ---------------------------------------------------------------------------
// Kernel B2: er_max[h] = max_n er[h,n]
// ---------------------------------------------------------------------------
__global__ void __launch_bounds__(256) ermax_kernel()
{
    __shared__ float red[256];
    int hh = blockIdx.x;
    float m = -1e30f;
    for (int i = threadIdx.x; i < NN; i += 256)
        m = fmaxf(m, g_er[hh * NN + i]);
    red[threadIdx.x] = m;
    __syncthreads();
    for (int s = 128; s > 0; s >>= 1) {
        if (threadIdx.x < s)
            red[threadIdx.x] = fmaxf(red[threadIdx.x], red[threadIdx.x + s]);
        __syncthreads();
    }
    if (threadIdx.x == 0) g_ermax[hh] = red[0];
}

// ---------------------------------------------------------------------------
// Kernel C: fused masked-softmax attention + P@Wh + ELU.
// Per CTA: one head, 64 query rows, all 64 output features.
// Single-pass softmax: c_i = lrelu(el_i + er_max) is an exact upper bound of
// the row max (lrelu is monotone), so exp args are always <= 0 -> no online
// rescaling needed. Masked entries contribute exactly 0 (matches reference:
// exp(-9e15 - max) == 0 in fp32).
// 128 threads; GEMM micro-tile 8 rows x 4 cols per thread over 64-wide j tiles.
// ---------------------------------------------------------------------------
__global__ void __launch_bounds__(128) gat_attn_kernel(
    const int* __restrict__ mask, float* __restrict__ out)
{
    __shared__ float Whs[64 * 68];   // [kk][c], padded
    __shared__ float ps[64 * 68];    // [kk][r], padded
    __shared__ float els[64];
    __shared__ float cs[64];
    __shared__ float ers[64];
    __shared__ float spart[128];
    __shared__ float srow[64];

    const int t   = threadIdx.x;
    const int i0  = blockIdx.x * 64;
    const int hh  = blockIdx.y;
    const int rg  = t >> 4, cg = t & 15;   // GEMM mapping: rows 8*rg.., cols 4*cg..
    const int pk  = t & 63, prr = t >> 6;  // p-phase mapping: k = pk, row half prr

    if (t < 64) {
        float e = g_el[(size_t)hh * NN + i0 + t];
        els[t] = e;
        float x = e + g_ermax[hh];
        cs[t] = fmaxf(x, ALPHA * x);
    }

    float acc[8][4];
#pragma unroll
    for (int i = 0; i < 8; i++)
#pragma unroll
        for (int j = 0; j < 4; j++) acc[i][j] = 0.f;
    float srun = 0.f;

    const float* Whb  = g_Wh + (size_t)hh * NN * FO;
    const float* erb  = g_er + (size_t)hh * NN;
    const int*   mkb  = mask + (size_t)i0 * NN;

    for (int j0 = 0; j0 < NN; j0 += 64) {
        if (t < 64) ers[t] = erb[j0 + t];
#pragma unroll
        for (int it = 0; it < 8; it++) {
            int idx = t + 128 * it;      // float4 index over 64x64 tile
            int kk = idx >> 4, c4 = idx & 15;
            *(float4*)(Whs + kk * 68 + 4 * c4) =
                *(const float4*)(Whb + (size_t)(j0 + kk) * FO + 4 * c4);
        }
        __syncthreads();

        // ---- score phase: p[kk][r] for this 64x64 tile ----
        {
            float erk = ers[pk];
            const int* mrow = mkb + (size_t)(prr * 32) * NN + j0 + pk;
#pragma unroll
            for (int m = 0; m < 32; m++) {
                int r = prr * 32 + m;
                float x = els[r] + erk;
                float l = fmaxf(x, ALPHA * x);
                int mk = mrow[(size_t)m * NN];
                float p = (mk > 0) ? __expf(l - cs[r]) : 0.f;
                ps[pk * 68 + r] = p;
            }
        }
        __syncthreads();

        // ---- partial row sums (each thread: half the k range of one row) ----
        {
            int r = t & 63, hf = t >> 6;
            const float* pp = ps + hf * 32 * 68 + r;
            float s = 0.f;
#pragma unroll
            for (int kk = 0; kk < 32; kk++) s += pp[kk * 68];
            spart[t] = s;
        }

        // ---- GEMM phase: acc += P_tile @ Wh_tile ----
#pragma unroll 8
        for (int kk = 0; kk < 64; kk++) {
            float4 p0 = *(const float4*)(ps + kk * 68 + 8 * rg);
            float4 p1 = *(const float4*)(ps + kk * 68 + 8 * rg + 4);
            float4 w  = *(const float4*)(Whs + kk * 68 + 4 * cg);
            float pr[8] = {p0.x, p0.y, p0.z, p0.w, p1.x, p1.y, p1.z, p1.w};
            float wr[4] = {w.x, w.y, w.z, w.w};
#pragma unroll
            for (int i = 0; i < 8; i++)
#pragma unroll
                for (int j = 0; j < 4; j++)
                    acc[i][j] += pr[i] * wr[j];
        }
        __syncthreads();

        if (t < 64) srun += spart[t] + spart[t + 64];
    }

    if (t < 64) srow[t] = srun;
    __syncthreads();

    float* ob = out + (size_t)(i0 + 8 * rg) * OUTW + hh * FO + 4 * cg;
#pragma unroll
    for (int i = 0; i < 8; i++) {
        float inv = 1.f / srow[8 * rg + i];
        float v0 = acc[i][0] * inv;
        float v1 = acc[i][1] * inv;
        float v2 = acc[i][2] * inv;
        float v3 = acc[i][3] * inv;
        float4 o;
        o.x = v0 > 0.f ? v0 : (__expf(v0) - 1.f);
        o.y = v1 > 0.f ? v1 : (__expf(v1) - 1.f);
        o.z = v2 > 0.f ? v2 : (__expf(v2) - 1.f);
        o.w = v3 > 0.f ? v3 : (__expf(v3) - 1.f);
        *(float4*)(ob + (size_t)i * OUTW) = o;
    }
}

// ---------------------------------------------------------------------------
extern "C" void kernel_launch(void* const* d_in, const int* in_sizes, int n_in,
                              void* d_out, int out_size)
{
    const float* h    = (const float*)d_in[0];  // [N, FIN]
    const int*   mask = (const int*)  d_in[1];  // [N, N]
    const float* W    = (const float*)d_in[2];  // [H, FIN, FO]
    const float* bW   = (const float*)d_in[3];  // [H, FO]
    const float* a_l  = (const float*)d_in[4];  // [H, FO]
    const float* a_r  = (const float*)d_in[5];  // [H, FO]
    const float* bA   = (const float*)d_in[6];  // [H]
    float* out = (float*)d_out;                 // [N, H*FO]

    wh_gemm_kernel<<<dim3(NN / 64, NH), 128>>>(h, W, bW);
    eler_kernel<<<(NH * NN) / 8, 256>>>(a_l, a_r, bA);
    ermax_kernel<<<NH, 256>>>();
    gat_attn_kernel<<<dim3(NN / 64, NH), 128>>>(mask, out);
}

// round 3
// speedup vs baseline: 1.6290x; 1.6290x over previous
#include <cuda_runtime.h>
#include <cuda_bf16.h>
#include <cstdint>

#define NN 4096
#define FIN 512
#define FO 64
#define NH 8
#define ALPHA 0.2f
#define OUTW (NH * FO)  /* 512 */

// ---------------------------------------------------------------------------
// Scratch (static device globals)
// ---------------------------------------------------------------------------
__device__ unsigned short g_bhi[NH * NN * FO];  // bf16 hi of Wh, [h][n][o]
__device__ unsigned short g_blo[NH * NN * FO];  // bf16 lo of Wh, [h][n][o]
__device__ float g_el[NH * NN];
__device__ float g_er[NH * NN];
__device__ float g_ermax[NH];

__device__ __forceinline__ uint32_t smem_u32(const void* p) {
    uint32_t a;
    asm("{ .reg .u64 t; cvta.to.shared.u64 t, %1; cvt.u32.u64 %0, t; }" : "=r"(a) : "l"(p));
    return a;
}

#define MMA16816(acc, a0, a1, a2, a3, b0, b1) \
    asm volatile("mma.sync.aligned.m16n8k16.row.col.f32.bf16.bf16.f32 " \
        "{%0,%1,%2,%3}, {%4,%5,%6,%7}, {%8,%9}, {%0,%1,%2,%3};" \
        : "+f"((acc)[0]), "+f"((acc)[1]), "+f"((acc)[2]), "+f"((acc)[3]) \
        : "r"(a0), "r"(a1), "r"(a2), "r"(a3), "r"(b0), "r"(b1))

#define LDSM4T(r0, r1, r2, r3, a) \
    asm volatile("ldmatrix.sync.aligned.m8n8.x4.trans.shared.b16 {%0,%1,%2,%3}, [%4];" \
        : "=r"(r0), "=r"(r1), "=r"(r2), "=r"(r3) : "r"(a))

#define LDSM2T(r0, r1, a) \
    asm volatile("ldmatrix.sync.aligned.m8n8.x2.trans.shared.b16 {%0,%1}, [%2];" \
        : "=r"(r0), "=r"(r1) : "r"(a))

// ---------------------------------------------------------------------------
// Kernel A: Wh = h @ W + bW (fp32 in regs); emit bf16 hi/lo [h][n][o] and
// fused el/er per row.
// grid (NN/64, NH), 128 threads, 64x64 tile, 8x4 per thread.
// ---------------------------------------------------------------------------
__global__ void __launch_bounds__(128) wh_gemm_kernel(
    const float* __restrict__ hmat, const float* __restrict__ W,
    const float* __restrict__ bW, const float* __restrict__ a_l,
    const float* __restrict__ a_r, const float* __restrict__ bA)
{
    __shared__ float As[16 * 68];
    __shared__ float Bs[16 * 68];
    const int t  = threadIdx.x;
    const int i0 = blockIdx.x * 64;
    const int hh = blockIdx.y;
    const int rg = t >> 4, cg = t & 15;
    const float* Wp = W + hh * (FIN * FO);

    float acc[8][4];
#pragma unroll
    for (int i = 0; i < 8; i++)
#pragma unroll
        for (int j = 0; j < 4; j++) acc[i][j] = 0.f;

    const int lkk = t & 15;
    const int lr  = t >> 4;

    for (int k0 = 0; k0 < FIN; k0 += 16) {
#pragma unroll
        for (int it = 0; it < 8; it++) {
            int r = lr + 8 * it;
            As[lkk * 68 + r] = hmat[(size_t)(i0 + r) * FIN + k0 + lkk];
        }
#pragma unroll
        for (int it = 0; it < 8; it++) {
            int idx = t + 128 * it;
            int kk = idx >> 6, c = idx & 63;
            Bs[kk * 68 + c] = Wp[(k0 + kk) * FO + c];
        }
        __syncthreads();
#pragma unroll
        for (int kk = 0; kk < 16; kk++) {
            float4 a0 = *(const float4*)(As + kk * 68 + 8 * rg);
            float4 a1 = *(const float4*)(As + kk * 68 + 8 * rg + 4);
            float4 b  = *(const float4*)(Bs + kk * 68 + 4 * cg);
            float ar[8] = {a0.x, a0.y, a0.z, a0.w, a1.x, a1.y, a1.z, a1.w};
            float br[4] = {b.x, b.y, b.z, b.w};
#pragma unroll
            for (int i = 0; i < 8; i++)
#pragma unroll
                for (int j = 0; j < 4; j++)
                    acc[i][j] += ar[i] * br[j];
        }
        __syncthreads();
    }

    float4 bw = *(const float4*)(bW + hh * FO + 4 * cg);
#pragma unroll
    for (int i = 0; i < 8; i++) {
        acc[i][0] += bw.x; acc[i][1] += bw.y; acc[i][2] += bw.z; acc[i][3] += bw.w;
    }

    // bf16 hi/lo stores, [h][n][o]
#pragma unroll
    for (int i = 0; i < 8; i++) {
        int r = i0 + 8 * rg + i;
        unsigned short hb[4], lb[4];
#pragma unroll
        for (int j = 0; j < 4; j++) {
            float v = acc[i][j];
            __nv_bfloat16 h16 = __float2bfloat16(v);
            hb[j] = __bfloat16_as_ushort(h16);
            lb[j] = __bfloat16_as_ushort(__float2bfloat16(v - __bfloat162float(h16)));
        }
        size_t base = ((size_t)hh * NN + r) * FO + 4 * cg;
        uint2 hv, lv;
        hv.x = hb[0] | ((uint32_t)hb[1] << 16);
        hv.y = hb[2] | ((uint32_t)hb[3] << 16);
        lv.x = lb[0] | ((uint32_t)lb[1] << 16);
        lv.y = lb[2] | ((uint32_t)lb[3] << 16);
        *(uint2*)(g_bhi + base) = hv;
        *(uint2*)(g_blo + base) = lv;
    }

    // fused el/er
    float4 alv = *(const float4*)(a_l + hh * FO + 4 * cg);
    float4 arv = *(const float4*)(a_r + hh * FO + 4 * cg);
#pragma unroll
    for (int i = 0; i < 8; i++) {
        float dl = acc[i][0] * alv.x + acc[i][1] * alv.y + acc[i][2] * alv.z + acc[i][3] * alv.w;
        float dr = acc[i][0] * arv.x + acc[i][1] * arv.y + acc[i][2] * arv.z + acc[i][3] * arv.w;
#pragma unroll
        for (int off = 8; off > 0; off >>= 1) {
            dl += __shfl_xor_sync(0xffffffffu, dl, off);
            dr += __shfl_xor_sync(0xffffffffu, dr, off);
        }
        if (cg == 0) {
            int r = i0 + 8 * rg + i;
            g_el[hh * NN + r] = dl + bA[hh];
            g_er[hh * NN + r] = dr;
        }
    }
}

// ---------------------------------------------------------------------------
// Kernel B: er_max[h]
// ---------------------------------------------------------------------------
__global__ void __launch_bounds__(256) ermax_kernel()
{
    __shared__ float red[256];
    int hh = blockIdx.x;
    float m = -1e30f;
    for (int i = threadIdx.x; i < NN; i += 256)
        m = fmaxf(m, g_er[hh * NN + i]);
    red[threadIdx.x] = m;
    __syncthreads();
    for (int s = 128; s > 0; s >>= 1) {
        if (threadIdx.x < s)
            red[threadIdx.x] = fmaxf(red[threadIdx.x], red[threadIdx.x + s]);
        __syncthreads();
    }
    if (threadIdx.x == 0) g_ermax[hh] = red[0];
}

// ---------------------------------------------------------------------------
// Kernel C: HMMA flash-GAT.
// CTA = (128 i-rows, 1 head), 8 warps x 16 rows. Accumulators in registers:
// acc[9][4] per lane = 16x72 per warp (72 = 64 feats + ones-col denom + pad).
// P computed straight into mma A fragments (no smem round trip).
// D = P_bf16 @ (W_hi + W_lo); denominator accumulates in col 64 via the
// ones column of W_hi.
// ---------------------------------------------------------------------------
__device__ __forceinline__ uint32_t pscore(float2 ec, float2 er, int2 m) {
    float x0 = ec.x + er.x;
    float l0 = fmaxf(x0, ALPHA * x0);
    float p0 = (m.x > 0) ? __expf(l0 - ec.y) : 0.f;
    float x1 = ec.x + er.y;
    float l1 = fmaxf(x1, ALPHA * x1);
    float p1 = (m.y > 0) ? __expf(l1 - ec.y) : 0.f;
    uint32_t r;
    asm("cvt.rn.bf16x2.f32 %0, %1, %2;" : "=r"(r) : "f"(p1), "f"(p0));
    return r;
}

__device__ __forceinline__ float elu(float v) {
    return v > 0.f ? v : (__expf(v) - 1.f);
}

#define BSTRIDE 72  /* bf16 elems per smem B row (144 B, 16B-aligned, ldsm conflict-free) */

__global__ void __launch_bounds__(256, 2) gat_attn_mma_kernel(
    const int* __restrict__ mask, float* __restrict__ out)
{
    __shared__ __align__(16) unsigned short Bhi[64 * BSTRIDE];
    __shared__ __align__(16) unsigned short Blo[64 * BSTRIDE];
    __shared__ float2 els2[128];

    const int t    = threadIdx.x;
    const int warp = t >> 5;
    const int lane = t & 31;
    const int i0   = blockIdx.x * 128;
    const int hh   = blockIdx.y;

    if (t < 128) {
        float e = g_el[hh * NN + i0 + t];
        float x = e + g_ermax[hh];
        els2[t] = make_float2(e, fmaxf(x, ALPHA * x));
    }
    // ones column (col 64) + zero pad (65..71), written once
    if (t < 64) {
        *(uint4*)&Bhi[t * BSTRIDE + 64] = make_uint4(0x00003F80u, 0u, 0u, 0u);
        *(uint4*)&Blo[t * BSTRIDE + 64] = make_uint4(0u, 0u, 0u, 0u);
    }
    __syncthreads();

    const int q  = lane >> 2;        // row group 0..7
    const int c2 = 2 * (lane & 3);   // col pair base
    const int rw0 = 16 * warp + q;   // local row (and +8)
    const float2 ec0 = els2[rw0];
    const float2 ec1 = els2[rw0 + 8];

    const int* mrow0 = mask + (size_t)(i0 + rw0) * NN + c2;
    const int* mrow1 = mrow0 + (size_t)8 * NN;
    const float* erb = g_er + hh * NN + c2;
    const unsigned short* ghi = g_bhi + (size_t)hh * NN * FO;
    const unsigned short* glo = g_blo + (size_t)hh * NN * FO;

    const uint32_t bhiBase = smem_u32(Bhi);
    const uint32_t bloBase = smem_u32(Blo);
    // ldmatrix lane address core: row (lane&15), +16B for lanes 16..31 (n0+8 half)
    const uint32_t lrowOff = (uint32_t)(lane & 15) * (BSTRIDE * 2) + ((lane & 16) ? 16 : 0);

    float acc[9][4];
#pragma unroll
    for (int n = 0; n < 9; n++)
#pragma unroll
        for (int j = 0; j < 4; j++) acc[n][j] = 0.f;

    for (int tile = 0; tile < NN / 64; tile++) {
        const int j0 = tile * 64;
        __syncthreads();
        // load B tile (64 rows x 64 cols, hi+lo)
#pragma unroll
        for (int it = 0; it < 2; it++) {
            int id = t + 256 * it;
            int k = id >> 3, c = id & 7;
            size_t src = ((size_t)(j0 + k)) * FO + c * 8;
            *(uint4*)&Bhi[k * BSTRIDE + c * 8] = *(const uint4*)(ghi + src);
            *(uint4*)&Blo[k * BSTRIDE + c * 8] = *(const uint4*)(glo + src);
        }
        __syncthreads();

#pragma unroll
        for (int kt = 0; kt < 4; kt++) {
            const int jb = j0 + 16 * kt;
            float2 e0 = *(const float2*)(erb + jb);
            float2 e1 = *(const float2*)(erb + jb + 8);
            int2 m00 = *(const int2*)(mrow0 + jb);
            int2 m01 = *(const int2*)(mrow0 + jb + 8);
            int2 m10 = *(const int2*)(mrow1 + jb);
            int2 m11 = *(const int2*)(mrow1 + jb + 8);
            uint32_t a0 = pscore(ec0, e0, m00);
            uint32_t a1 = pscore(ec1, e0, m10);
            uint32_t a2 = pscore(ec0, e1, m01);
            uint32_t a3 = pscore(ec1, e1, m11);

            const uint32_t kOff = (uint32_t)(16 * kt) * (BSTRIDE * 2) + lrowOff;
#pragma unroll
            for (int ntp = 0; ntp < 4; ntp++) {
                uint32_t b0, b1, b2, b3;
                LDSM4T(b0, b1, b2, b3, bhiBase + kOff + 32 * ntp);
                MMA16816(acc[2 * ntp],     a0, a1, a2, a3, b0, b1);
                MMA16816(acc[2 * ntp + 1], a0, a1, a2, a3, b2, b3);
                LDSM4T(b0, b1, b2, b3, bloBase + kOff + 32 * ntp);
                MMA16816(acc[2 * ntp],     a0, a1, a2, a3, b0, b1);
                MMA16816(acc[2 * ntp + 1], a0, a1, a2, a3, b2, b3);
            }
            {   // ones-column tile (denominator)
                uint32_t b0, b1;
                LDSM2T(b0, b1, bhiBase + kOff + 128);
                MMA16816(acc[8], a0, a1, a2, a3, b0, b1);
            }
        }
    }

    // ---- epilogue ----
    const int src = lane & ~3;  // lane holding cols 64,65 for this row group
    float inv0 = 1.f / __shfl_sync(0xffffffffu, acc[8][0], src);
    float inv1 = 1.f / __shfl_sync(0xffffffffu, acc[8][2], src);

    float* ob0 = out + (size_t)(i0 + rw0) * OUTW + hh * FO + c2;
    float* ob1 = ob0 + (size_t)8 * OUTW;
#pragma unroll
    for (int nt = 0; nt < 8; nt++) {
        float2 v0 = make_float2(elu(acc[nt][0] * inv0), elu(acc[nt][1] * inv0));
        float2 v1 = make_float2(elu(acc[nt][2] * inv1), elu(acc[nt][3] * inv1));
        *(float2*)(ob0 + 8 * nt) = v0;
        *(float2*)(ob1 + 8 * nt) = v1;
    }
}

// ---------------------------------------------------------------------------
extern "C" void kernel_launch(void* const* d_in, const int* in_sizes, int n_in,
                              void* d_out, int out_size)
{
    const float* h    = (const float*)d_in[0];  // [N, FIN]
    const int*   mask = (const int*)  d_in[1];  // [N, N]
    const float* W    = (const float*)d_in[2];  // [H, FIN, FO]
    const float* bW   = (const float*)d_in[3];  // [H, FO]
    const float* a_l  = (const float*)d_in[4];  // [H, FO]
    const float* a_r  = (const float*)d_in[5];  // [H, FO]
    const float* bA   = (const float*)d_in[6];  // [H]
    float* out = (float*)d_out;                 // [N, H*FO]

    wh_gemm_kernel<<<dim3(NN / 64, NH), 128>>>(h, W, bW, a_l, a_r, bA);
    ermax_kernel<<<NH, 256>>>();
    gat_attn_mma_kernel<<<dim3(NN / 128, NH), 256>>>(mask, out);
}

// round 4
// speedup vs baseline: 1.8017x; 1.1060x over previous
#include <cuda_runtime.h>
#include <cuda_fp16.h>
#include <cuda_bf16.h>
#include <cstdint>

#define NN 4096
#define FIN 512
#define FO 64
#define NH 8
#define ALPHA 0.2f
#define OUTW (NH * FO)  /* 512 */

// ---------------------------------------------------------------------------
// Scratch (static device globals)
// ---------------------------------------------------------------------------
__device__ unsigned short g_wh16[NH * NN * FO];  // fp16 Wh, [h][n][o]
__device__ float g_el[NH * NN];
__device__ float g_er[NH * NN];
__device__ float g_ermax[NH];

__device__ __forceinline__ uint32_t smem_u32(const void* p) {
    uint32_t a;
    asm("{ .reg .u64 t; cvta.to.shared.u64 t, %1; cvt.u32.u64 %0, t; }" : "=r"(a) : "l"(p));
    return a;
}

#define MMA16816F16(acc, a0, a1, a2, a3, b0, b1) \
    asm volatile("mma.sync.aligned.m16n8k16.row.col.f32.f16.f16.f32 " \
        "{%0,%1,%2,%3}, {%4,%5,%6,%7}, {%8,%9}, {%0,%1,%2,%3};" \
        : "+f"((acc)[0]), "+f"((acc)[1]), "+f"((acc)[2]), "+f"((acc)[3]) \
        : "r"(a0), "r"(a1), "r"(a2), "r"(a3), "r"(b0), "r"(b1))

#define LDSM4T(r0, r1, r2, r3, a) \
    asm volatile("ldmatrix.sync.aligned.m8n8.x4.trans.shared.b16 {%0,%1,%2,%3}, [%4];" \
        : "=r"(r0), "=r"(r1), "=r"(r2), "=r"(r3) : "r"(a))

// ---------------------------------------------------------------------------
// Kernel A: Wh = h @ W + bW (fp32 in regs); emit fp16 [h][n][o] and fused
// el/er per row.  grid (NN/64, NH), 128 threads, 64x64 tile, 8x4 per thread.
// ---------------------------------------------------------------------------
__global__ void __launch_bounds__(128) wh_gemm_kernel(
    const float* __restrict__ hmat, const float* __restrict__ W,
    const float* __restrict__ bW, const float* __restrict__ a_l,
    const float* __restrict__ a_r, const float* __restrict__ bA)
{
    __shared__ float As[16 * 68];
    __shared__ float Bs[16 * 68];
    const int t  = threadIdx.x;
    const int i0 = blockIdx.x * 64;
    const int hh = blockIdx.y;
    const int rg = t >> 4, cg = t & 15;
    const float* Wp = W + hh * (FIN * FO);

    float acc[8][4];
#pragma unroll
    for (int i = 0; i < 8; i++)
#pragma unroll
        for (int j = 0; j < 4; j++) acc[i][j] = 0.f;

    const int lkk = t & 15;
    const int lr  = t >> 4;

    for (int k0 = 0; k0 < FIN; k0 += 16) {
#pragma unroll
        for (int it = 0; it < 8; it++) {
            int r = lr + 8 * it;
            As[lkk * 68 + r] = hmat[(size_t)(i0 + r) * FIN + k0 + lkk];
        }
#pragma unroll
        for (int it = 0; it < 8; it++) {
            int idx = t + 128 * it;
            int kk = idx >> 6, c = idx & 63;
            Bs[kk * 68 + c] = Wp[(k0 + kk) * FO + c];
        }
        __syncthreads();
#pragma unroll
        for (int kk = 0; kk < 16; kk++) {
            float4 a0 = *(const float4*)(As + kk * 68 + 8 * rg);
            float4 a1 = *(const float4*)(As + kk * 68 + 8 * rg + 4);
            float4 b  = *(const float4*)(Bs + kk * 68 + 4 * cg);
            float ar[8] = {a0.x, a0.y, a0.z, a0.w, a1.x, a1.y, a1.z, a1.w};
            float br[4] = {b.x, b.y, b.z, b.w};
#pragma unroll
            for (int i = 0; i < 8; i++)
#pragma unroll
                for (int j = 0; j < 4; j++)
                    acc[i][j] += ar[i] * br[j];
        }
        __syncthreads();
    }

    float4 bw = *(const float4*)(bW + hh * FO + 4 * cg);
#pragma unroll
    for (int i = 0; i < 8; i++) {
        acc[i][0] += bw.x; acc[i][1] += bw.y; acc[i][2] += bw.z; acc[i][3] += bw.w;
    }

    // fp16 stores, [h][n][o]
#pragma unroll
    for (int i = 0; i < 8; i++) {
        int r = i0 + 8 * rg + i;
        uint32_t w0, w1;
        asm("cvt.rn.f16x2.f32 %0, %1, %2;" : "=r"(w0) : "f"(acc[i][1]), "f"(acc[i][0]));
        asm("cvt.rn.f16x2.f32 %0, %1, %2;" : "=r"(w1) : "f"(acc[i][3]), "f"(acc[i][2]));
        *(uint2*)(g_wh16 + ((size_t)hh * NN + r) * FO + 4 * cg) = make_uint2(w0, w1);
    }

    // fused el/er
    float4 alv = *(const float4*)(a_l + hh * FO + 4 * cg);
    float4 arv = *(const float4*)(a_r + hh * FO + 4 * cg);
#pragma unroll
    for (int i = 0; i < 8; i++) {
        float dl = acc[i][0] * alv.x + acc[i][1] * alv.y + acc[i][2] * alv.z + acc[i][3] * alv.w;
        float dr = acc[i][0] * arv.x + acc[i][1] * arv.y + acc[i][2] * arv.z + acc[i][3] * arv.w;
#pragma unroll
        for (int off = 8; off > 0; off >>= 1) {
            dl += __shfl_xor_sync(0xffffffffu, dl, off);
            dr += __shfl_xor_sync(0xffffffffu, dr, off);
        }
        if (cg == 0) {
            int r = i0 + 8 * rg + i;
            g_el[hh * NN + r] = dl + bA[hh];
            g_er[hh * NN + r] = dr;
        }
    }
}

// ---------------------------------------------------------------------------
// Kernel B: er_max[h]
// ---------------------------------------------------------------------------
__global__ void __launch_bounds__(256) ermax_kernel()
{
    __shared__ float red[256];
    int hh = blockIdx.x;
    float m = -1e30f;
    for (int i = threadIdx.x; i < NN; i += 256)
        m = fmaxf(m, g_er[hh * NN + i]);
    red[threadIdx.x] = m;
    __syncthreads();
    for (int s = 128; s > 0; s >>= 1) {
        if (threadIdx.x < s)
            red[threadIdx.x] = fmaxf(red[threadIdx.x], red[threadIdx.x + s]);
        __syncthreads();
    }
    if (threadIdx.x == 0) g_ermax[hh] = red[0];
}

// ---------------------------------------------------------------------------
// Kernel C: fp16 HMMA flash-GAT.
// CTA = (128 i-rows, 1 head), 8 warps x 16 rows. acc[8][4] per lane = 16x64
// per warp. P computed straight into fp16 mma A fragments; the softmax
// denominator accumulates in fp32 SIMT (per-lane partial sums + quad reduce),
// so there is exactly ONE fp16 GEMM: D = P @ Wh16.
// ---------------------------------------------------------------------------
__device__ __forceinline__ float elu(float v) {
    return v > 0.f ? v : (__expf(v) - 1.f);
}

// p-pair for one row against two j's; returns packed fp16x2 and adds to sum.
__device__ __forceinline__ uint32_t pscore(float2 ec, float2 er, int2 m, float& sum) {
    float x0 = ec.x + er.x;
    float l0 = fmaxf(x0, ALPHA * x0);
    float p0 = (m.x > 0) ? __expf(l0 - ec.y) : 0.f;
    float x1 = ec.x + er.y;
    float l1 = fmaxf(x1, ALPHA * x1);
    float p1 = (m.y > 0) ? __expf(l1 - ec.y) : 0.f;
    sum += p0 + p1;
    uint32_t r;
    asm("cvt.rn.f16x2.f32 %0, %1, %2;" : "=r"(r) : "f"(p1), "f"(p0));
    return r;
}

#define BSTRIDE 72  /* fp16 elems per smem B row (144 B, ldsm conflict-free) */

__global__ void __launch_bounds__(256, 2) gat_attn_mma_kernel(
    const int* __restrict__ mask, float* __restrict__ out)
{
    __shared__ __align__(16) unsigned short Bs[64 * BSTRIDE];
    __shared__ float2 els2[128];

    const int t    = threadIdx.x;
    const int warp = t >> 5;
    const int lane = t & 31;
    const int i0   = blockIdx.x * 128;
    const int hh   = blockIdx.y;

    if (t < 128) {
        float e = g_el[hh * NN + i0 + t];
        float x = e + g_ermax[hh];
        els2[t] = make_float2(e, fmaxf(x, ALPHA * x));
    }
    __syncthreads();

    const int q  = lane >> 2;        // row group 0..7
    const int c2 = 2 * (lane & 3);   // col pair base
    const int rw0 = 16 * warp + q;   // local row (and +8)
    const float2 ec0 = els2[rw0];
    const float2 ec1 = els2[rw0 + 8];

    const int* mrow0 = mask + (size_t)(i0 + rw0) * NN + c2;
    const int* mrow1 = mrow0 + (size_t)8 * NN;
    const float* erb = g_er + hh * NN + c2;
    const unsigned short* gwh = g_wh16 + (size_t)hh * NN * FO;

    const uint32_t bBase = smem_u32(Bs);
    const uint32_t lrowOff = (uint32_t)(lane & 15) * (BSTRIDE * 2) + ((lane & 16) ? 16 : 0);

    float acc[8][4];
#pragma unroll
    for (int n = 0; n < 8; n++)
#pragma unroll
        for (int j = 0; j < 4; j++) acc[n][j] = 0.f;
    float sum0 = 0.f, sum1 = 0.f;

    for (int tile = 0; tile < NN / 64; tile++) {
        const int j0 = tile * 64;
        __syncthreads();
        // load B tile (64 rows x 64 fp16): 512 uint4, 2 per thread
#pragma unroll
        for (int it = 0; it < 2; it++) {
            int id = t + 256 * it;
            int k = id >> 3, c = id & 7;
            *(uint4*)&Bs[k * BSTRIDE + c * 8] =
                *(const uint4*)(gwh + ((size_t)(j0 + k)) * FO + c * 8);
        }
        __syncthreads();

#pragma unroll
        for (int kt = 0; kt < 4; kt++) {
            const int jb = j0 + 16 * kt;
            float2 e0 = *(const float2*)(erb + jb);
            float2 e1 = *(const float2*)(erb + jb + 8);
            int2 m00 = *(const int2*)(mrow0 + jb);
            int2 m01 = *(const int2*)(mrow0 + jb + 8);
            int2 m10 = *(const int2*)(mrow1 + jb);
            int2 m11 = *(const int2*)(mrow1 + jb + 8);
            uint32_t a0 = pscore(ec0, e0, m00, sum0);
            uint32_t a1 = pscore(ec1, e0, m10, sum1);
            uint32_t a2 = pscore(ec0, e1, m01, sum0);
            uint32_t a3 = pscore(ec1, e1, m11, sum1);

            const uint32_t kOff = (uint32_t)(16 * kt) * (BSTRIDE * 2) + lrowOff;
#pragma unroll
            for (int ntp = 0; ntp < 4; ntp++) {
                uint32_t b0, b1, b2, b3;
                LDSM4T(b0, b1, b2, b3, bBase + kOff + 32 * ntp);
                MMA16816F16(acc[2 * ntp],     a0, a1, a2, a3, b0, b1);
                MMA16816F16(acc[2 * ntp + 1], a0, a1, a2, a3, b2, b3);
            }
        }
    }

    // ---- epilogue: quad-reduce denominators (lanes sharing a row group) ----
    sum0 += __shfl_xor_sync(0xffffffffu, sum0, 1);
    sum0 += __shfl_xor_sync(0xffffffffu, sum0, 2);
    sum1 += __shfl_xor_sync(0xffffffffu, sum1, 1);
    sum1 += __shfl_xor_sync(0xffffffffu, sum1, 2);
    const float inv0 = 1.f / sum0;
    const float inv1 = 1.f / sum1;

    float* ob0 = out + (size_t)(i0 + rw0) * OUTW + hh * FO + c2;
    float* ob1 = ob0 + (size_t)8 * OUTW;
#pragma unroll
    for (int nt = 0; nt < 8; nt++) {
        float2 v0 = make_float2(elu(acc[nt][0] * inv0), elu(acc[nt][1] * inv0));
        float2 v1 = make_float2(elu(acc[nt][2] * inv1), elu(acc[nt][3] * inv1));
        *(float2*)(ob0 + 8 * nt) = v0;
        *(float2*)(ob1 + 8 * nt) = v1;
    }
}

// ---------------------------------------------------------------------------
extern "C" void kernel_launch(void* const* d_in, const int* in_sizes, int n_in,
                              void* d_out, int out_size)
{
    const float* h    = (const float*)d_in[0];  // [N, FIN]
    const int*   mask = (const int*)  d_in[1];  // [N, N]
    const float* W    = (const float*)d_in[2];  // [H, FIN, FO]
    const float* bW   = (const float*)d_in[3];  // [H, FO]
    const float* a_l  = (const float*)d_in[4];  // [H, FO]
    const float* a_r  = (const float*)d_in[5];  // [H, FO]
    const float* bA   = (const float*)d_in[6];  // [H]
    float* out = (float*)d_out;                 // [N, H*FO]

    wh_gemm_kernel<<<dim3(NN / 64, NH), 128>>>(h, W, bW, a_l, a_r, bA);
    ermax_kernel<<<NH, 256>>>();
    gat_attn_mma_kernel<<<dim3(NN / 128, NH), 256>>>(mask, out);
}

// round 5
// speedup vs baseline: 2.9174x; 1.6192x over previous
#include <cuda_runtime.h>
#include <cuda_fp16.h>
#include <cstdint>

#define NN 4096
#define FIN 512
#define FO 64
#define NH 8
#define ALPHA 0.2f
#define OUTW (NH * FO)  /* 512 */
#define LOG2E 1.4426950408889634f
#define NWORD (NN / 32)  /* 128 */

// ---------------------------------------------------------------------------
// Scratch (static device globals)
// ---------------------------------------------------------------------------
__device__ unsigned short g_wh16[NH * NN * FO];  // fp16 Wh, [h][n][o]
__device__ float g_el[NH * NN];                  // el * log2e (incl bA)
__device__ float g_er[NH * NN];                  // er * log2e
__device__ float g_ermax[NH];
__device__ uint32_t g_bits[NN * NWORD];          // mask bitmap [i][j/32]

__device__ __forceinline__ uint32_t smem_u32(const void* p) {
    uint32_t a;
    asm("{ .reg .u64 t; cvta.to.shared.u64 t, %1; cvt.u32.u64 %0, t; }" : "=r"(a) : "l"(p));
    return a;
}

#define MMA16816F16(acc, a0, a1, a2, a3, b0, b1) \
    asm volatile("mma.sync.aligned.m16n8k16.row.col.f32.f16.f16.f32 " \
        "{%0,%1,%2,%3}, {%4,%5,%6,%7}, {%8,%9}, {%0,%1,%2,%3};" \
        : "+f"((acc)[0]), "+f"((acc)[1]), "+f"((acc)[2]), "+f"((acc)[3]) \
        : "r"(a0), "r"(a1), "r"(a2), "r"(a3), "r"(b0), "r"(b1))

#define LDSM4T(r0, r1, r2, r3, a) \
    asm volatile("ldmatrix.sync.aligned.m8n8.x4.trans.shared.b16 {%0,%1,%2,%3}, [%4];" \
        : "=r"(r0), "=r"(r1), "=r"(r2), "=r"(r3) : "r"(a))

// ---------------------------------------------------------------------------
// Kernel A: Wh = h @ W + bW (fp32 in regs); emit fp16 [h][n][o] and fused
// el/er (pre-scaled by log2e) per row.
// ---------------------------------------------------------------------------
__global__ void __launch_bounds__(128) wh_gemm_kernel(
    const float* __restrict__ hmat, const float* __restrict__ W,
    const float* __restrict__ bW, const float* __restrict__ a_l,
    const float* __restrict__ a_r, const float* __restrict__ bA)
{
    __shared__ float As[16 * 68];
    __shared__ float Bs[16 * 68];
    const int t  = threadIdx.x;
    const int i0 = blockIdx.x * 64;
    const int hh = blockIdx.y;
    const int rg = t >> 4, cg = t & 15;
    const float* Wp = W + hh * (FIN * FO);

    float acc[8][4];
#pragma unroll
    for (int i = 0; i < 8; i++)
#pragma unroll
        for (int j = 0; j < 4; j++) acc[i][j] = 0.f;

    const int lkk = t & 15;
    const int lr  = t >> 4;

    for (int k0 = 0; k0 < FIN; k0 += 16) {
#pragma unroll
        for (int it = 0; it < 8; it++) {
            int r = lr + 8 * it;
            As[lkk * 68 + r] = hmat[(size_t)(i0 + r) * FIN + k0 + lkk];
        }
#pragma unroll
        for (int it = 0; it < 8; it++) {
            int idx = t + 128 * it;
            int kk = idx >> 6, c = idx & 63;
            Bs[kk * 68 + c] = Wp[(k0 + kk) * FO + c];
        }
        __syncthreads();
#pragma unroll
        for (int kk = 0; kk < 16; kk++) {
            float4 a0 = *(const float4*)(As + kk * 68 + 8 * rg);
            float4 a1 = *(const float4*)(As + kk * 68 + 8 * rg + 4);
            float4 b  = *(const float4*)(Bs + kk * 68 + 4 * cg);
            float ar[8] = {a0.x, a0.y, a0.z, a0.w, a1.x, a1.y, a1.z, a1.w};
            float br[4] = {b.x, b.y, b.z, b.w};
#pragma unroll
            for (int i = 0; i < 8; i++)
#pragma unroll
                for (int j = 0; j < 4; j++)
                    acc[i][j] += ar[i] * br[j];
        }
        __syncthreads();
    }

    float4 bw = *(const float4*)(bW + hh * FO + 4 * cg);
#pragma unroll
    for (int i = 0; i < 8; i++) {
        acc[i][0] += bw.x; acc[i][1] += bw.y; acc[i][2] += bw.z; acc[i][3] += bw.w;
    }

    // fp16 stores, [h][n][o]
#pragma unroll
    for (int i = 0; i < 8; i++) {
        int r = i0 + 8 * rg + i;
        uint32_t w0, w1;
        asm("cvt.rn.f16x2.f32 %0, %1, %2;" : "=r"(w0) : "f"(acc[i][1]), "f"(acc[i][0]));
        asm("cvt.rn.f16x2.f32 %0, %1, %2;" : "=r"(w1) : "f"(acc[i][3]), "f"(acc[i][2]));
        *(uint2*)(g_wh16 + ((size_t)hh * NN + r) * FO + 4 * cg) = make_uint2(w0, w1);
    }

    // fused el/er (log2e-scaled; lrelu is positive-homogeneous so this commutes)
    float4 alv = *(const float4*)(a_l + hh * FO + 4 * cg);
    float4 arv = *(const float4*)(a_r + hh * FO + 4 * cg);
#pragma unroll
    for (int i = 0; i < 8; i++) {
        float dl = acc[i][0] * alv.x + acc[i][1] * alv.y + acc[i][2] * alv.z + acc[i][3] * alv.w;
        float dr = acc[i][0] * arv.x + acc[i][1] * arv.y + acc[i][2] * arv.z + acc[i][3] * arv.w;
#pragma unroll
        for (int off = 8; off > 0; off >>= 1) {
            dl += __shfl_xor_sync(0xffffffffu, dl, off);
            dr += __shfl_xor_sync(0xffffffffu, dr, off);
        }
        if (cg == 0) {
            int r = i0 + 8 * rg + i;
            g_el[hh * NN + r] = (dl + bA[hh]) * LOG2E;
            g_er[hh * NN + r] = dr * LOG2E;
        }
    }
}

// ---------------------------------------------------------------------------
// Kernel A2: mask -> bitmap
// ---------------------------------------------------------------------------
__global__ void __launch_bounds__(256) mask_bits_kernel(const int* __restrict__ mask)
{
    int gw   = (blockIdx.x * 256 + threadIdx.x) >> 5;  // word index 0..NN*NWORD-1
    int lane = threadIdx.x & 31;
    int row  = gw >> 7;          // /NWORD
    int wd   = gw & (NWORD - 1);
    int m = mask[(size_t)row * NN + wd * 32 + lane];
    uint32_t b = __ballot_sync(0xffffffffu, m > 0);
    if (lane == 0) g_bits[gw] = b;
}

// ---------------------------------------------------------------------------
// Kernel B: er_max[h] (on scaled er; scaling is monotone)
// ---------------------------------------------------------------------------
__global__ void __launch_bounds__(256) ermax_kernel()
{
    __shared__ float red[256];
    int hh = blockIdx.x;
    float m = -1e30f;
    for (int i = threadIdx.x; i < NN; i += 256)
        m = fmaxf(m, g_er[hh * NN + i]);
    red[threadIdx.x] = m;
    __syncthreads();
    for (int s = 128; s > 0; s >>= 1) {
        if (threadIdx.x < s)
            red[threadIdx.x] = fmaxf(red[threadIdx.x], red[threadIdx.x + s]);
        __syncthreads();
    }
    if (threadIdx.x == 0) g_ermax[hh] = red[0];
}

// ---------------------------------------------------------------------------
// Kernel C: fp16 HMMA flash-GAT with bitmask + ex2.f16x2 + double buffering.
// ---------------------------------------------------------------------------
__device__ __forceinline__ float elu(float v) {
    return v > 0.f ? v : (__expf(v) - 1.f);
}

// Two softmax numerators for one row vs two j's. All inputs log2e-scaled so
// p = exp2(lrelu(x) - c). Result masked via bit pair b2 (fp16 +0 is exact).
__device__ __forceinline__ uint32_t pscore2(float2 ec, float2 er, uint32_t b2, float& sum) {
    float x0 = ec.x + er.x;
    float a0 = fmaxf(x0, ALPHA * x0) - ec.y;
    float x1 = ec.x + er.y;
    float a1 = fmaxf(x1, ALPHA * x1) - ec.y;
    uint32_t ph, pe;
    asm("cvt.rn.f16x2.f32 %0, %1, %2;" : "=r"(ph) : "f"(a1), "f"(a0));
    asm("ex2.approx.f16x2 %0, %1;" : "=r"(pe) : "r"(ph));
    uint32_t msk = (b2 & 1u) * 0xFFFFu + (b2 & 2u) * 0x7FFF8000u;
    pe &= msk;
    __half2 hp = *reinterpret_cast<const __half2*>(&pe);
    float2 pf = __half22float2(hp);
    sum += pf.x + pf.y;
    return pe;
}

#define BSTRIDE 72  /* fp16 elems per smem B row (144 B, ldsm conflict-free) */

__global__ void __launch_bounds__(256, 2) gat_attn_mma_kernel(float* __restrict__ out)
{
    __shared__ __align__(16) unsigned short Bs[2][64 * BSTRIDE];
    __shared__ float2 els2[128];

    const int t    = threadIdx.x;
    const int warp = t >> 5;
    const int lane = t & 31;
    const int i0   = blockIdx.x * 128;
    const int hh   = blockIdx.y;

    if (t < 128) {
        float e = g_el[hh * NN + i0 + t];
        float x = e + g_ermax[hh];
        els2[t] = make_float2(e, fmaxf(x, ALPHA * x));
    }

    const int q  = lane >> 2;        // row group 0..7
    const int c2 = 2 * (lane & 3);   // col pair base
    const int rw0 = 16 * warp + q;   // local row (and +8)

    const float* erb = g_er + hh * NN + c2;
    const unsigned short* gwh = g_wh16 + (size_t)hh * NN * FO;
    const uint32_t* bitrow = g_bits + (size_t)(i0 + 16 * warp + (lane >> 1)) * NWORD + (lane & 1);

    const uint32_t bBase = smem_u32(Bs);
    const uint32_t lrowOff = (uint32_t)(lane & 15) * (BSTRIDE * 2) + ((lane & 16) ? 16 : 0);

    // load-index decomposition for B tiles (2 uint4 per thread)
    const int lk0 = t >> 3, lc0 = t & 7;
    const int lk1 = (t + 256) >> 3, lc1 = t & 7;

    float acc[8][4];
#pragma unroll
    for (int n = 0; n < 8; n++)
#pragma unroll
        for (int j = 0; j < 4; j++) acc[n][j] = 0.f;
    float sum0 = 0.f, sum1 = 0.f;

    // preload tile 0
    {
        uint4 va = *(const uint4*)(gwh + (size_t)lk0 * FO + lc0 * 8);
        uint4 vb = *(const uint4*)(gwh + (size_t)lk1 * FO + lc1 * 8);
        *(uint4*)&Bs[0][lk0 * BSTRIDE + lc0 * 8] = va;
        *(uint4*)&Bs[0][lk1 * BSTRIDE + lc1 * 8] = vb;
    }
    __syncthreads();

    const float2 ec0 = els2[rw0];
    const float2 ec1 = els2[rw0 + 8];

    for (int tile = 0; tile < NN / 64; tile++) {
        const int j0 = tile * 64;
        const int cur = tile & 1;

        // bitmask for this warp's 16 rows x 64 j: one u32/lane + 4 shfl
        uint32_t bv = bitrow[(uint32_t)(j0 >> 5)];
        uint32_t w00 = __shfl_sync(0xffffffffu, bv, 2 * q);
        uint32_t w01 = __shfl_sync(0xffffffffu, bv, 2 * q + 1);
        uint32_t w10 = __shfl_sync(0xffffffffu, bv, 2 * q + 16);
        uint32_t w11 = __shfl_sync(0xffffffffu, bv, 2 * q + 17);

        // prefetch next B tile into regs
        uint4 na, nb;
        if (tile < NN / 64 - 1) {
            const unsigned short* src = gwh + (size_t)(j0 + 64) * FO;
            na = *(const uint4*)(src + (size_t)lk0 * FO + lc0 * 8);
            nb = *(const uint4*)(src + (size_t)lk1 * FO + lc1 * 8);
        }

        const uint32_t bufOff = bBase + cur * (64 * BSTRIDE * 2) + lrowOff;

#pragma unroll
        for (int kt = 0; kt < 4; kt++) {
            const int jb = j0 + 16 * kt;
            float2 e0 = *(const float2*)(erb + jb);
            float2 e1 = *(const float2*)(erb + jb + 8);

            uint32_t wr0 = (kt < 2) ? w00 : w01;
            uint32_t wr1 = (kt < 2) ? w10 : w11;
            const int sb = (kt & 1) * 16;
            uint32_t b00 = (wr0 >> (sb + c2)) & 3u;
            uint32_t b01 = (wr0 >> (sb + 8 + c2)) & 3u;
            uint32_t b10 = (wr1 >> (sb + c2)) & 3u;
            uint32_t b11 = (wr1 >> (sb + 8 + c2)) & 3u;

            uint32_t a0 = pscore2(ec0, e0, b00, sum0);
            uint32_t a1 = pscore2(ec1, e0, b10, sum1);
            uint32_t a2 = pscore2(ec0, e1, b01, sum0);
            uint32_t a3 = pscore2(ec1, e1, b11, sum1);

            const uint32_t kOff = bufOff + (uint32_t)(16 * kt) * (BSTRIDE * 2);
#pragma unroll
            for (int ntp = 0; ntp < 4; ntp++) {
                uint32_t b0, b1, b2, b3;
                LDSM4T(b0, b1, b2, b3, kOff + 32 * ntp);
                MMA16816F16(acc[2 * ntp],     a0, a1, a2, a3, b0, b1);
                MMA16816F16(acc[2 * ntp + 1], a0, a1, a2, a3, b2, b3);
            }
        }

        if (tile < NN / 64 - 1) {
            unsigned short* dst = &Bs[cur ^ 1][0];
            *(uint4*)&dst[lk0 * BSTRIDE + lc0 * 8] = na;
            *(uint4*)&dst[lk1 * BSTRIDE + lc1 * 8] = nb;
        }
        __syncthreads();
    }

    // ---- epilogue: quad-reduce denominators ----
    sum0 += __shfl_xor_sync(0xffffffffu, sum0, 1);
    sum0 += __shfl_xor_sync(0xffffffffu, sum0, 2);
    sum1 += __shfl_xor_sync(0xffffffffu, sum1, 1);
    sum1 += __shfl_xor_sync(0xffffffffu, sum1, 2);
    const float inv0 = 1.f / sum0;
    const float inv1 = 1.f / sum1;

    float* ob0 = out + (size_t)(i0 + rw0) * OUTW + hh * FO + c2;
    float* ob1 = ob0 + (size_t)8 * OUTW;
#pragma unroll
    for (int nt = 0; nt < 8; nt++) {
        float2 v0 = make_float2(elu(acc[nt][0] * inv0), elu(acc[nt][1] * inv0));
        float2 v1 = make_float2(elu(acc[nt][2] * inv1), elu(acc[nt][3] * inv1));
        *(float2*)(ob0 + 8 * nt) = v0;
        *(float2*)(ob1 + 8 * nt) = v1;
    }
}

// ---------------------------------------------------------------------------
extern "C" void kernel_launch(void* const* d_in, const int* in_sizes, int n_in,
                              void* d_out, int out_size)
{
    const float* h    = (const float*)d_in[0];  // [N, FIN]
    const int*   mask = (const int*)  d_in[1];  // [N, N]
    const float* W    = (const float*)d_in[2];  // [H, FIN, FO]
    const float* bW   = (const float*)d_in[3];  // [H, FO]
    const float* a_l  = (const float*)d_in[4];  // [H, FO]
    const float* a_r  = (const float*)d_in[5];  // [H, FO]
    const float* bA   = (const float*)d_in[6];  // [H]
    float* out = (float*)d_out;                 // [N, H*FO]

    wh_gemm_kernel<<<dim3(NN / 64, NH), 128>>>(h, W, bW, a_l, a_r, bA);
    mask_bits_kernel<<<NN * NWORD / 8, 256>>>(mask);
    ermax_kernel<<<NH, 256>>>();
    gat_attn_mma_kernel<<<dim3(NN / 128, NH), 256>>>(out);
}

// round 6
// speedup vs baseline: 3.6204x; 1.2410x over previous
#include <cuda_runtime.h>
#include <cuda_fp16.h>
#include <cstdint>

#define NN 4096
#define FIN 512
#define FO 64
#define NH 8
#define ALPHA 0.2f
#define OUTW (NH * FO)  /* 512 */
#define LOG2E 1.4426950408889634f
#define NWORD (NN / 32)  /* 128 */

// ---------------------------------------------------------------------------
// Scratch (static device globals)
// ---------------------------------------------------------------------------
__device__ unsigned short g_h16hi[NN * FIN];     // fp16 hi of h, [n][k]
__device__ unsigned short g_h16lo[NN * FIN];     // fp16 lo of h, [n][k]
__device__ unsigned short g_w16hi[NH * FIN * FO];// fp16 hi of W, [h][k][n]
__device__ unsigned short g_w16lo[NH * FIN * FO];
__device__ unsigned short g_wh16[NH * NN * FO];  // fp16 Wh, [h][n][o]
__device__ float g_el[NH * NN];                  // el * log2e (incl bA)
__device__ float g_er[NH * NN];                  // er * log2e
__device__ float g_ermax[NH];
__device__ uint32_t g_bits[NN * NWORD];          // mask bitmap [i][j/32]

__device__ __forceinline__ uint32_t smem_u32(const void* p) {
    uint32_t a;
    asm("{ .reg .u64 t; cvta.to.shared.u64 t, %1; cvt.u32.u64 %0, t; }" : "=r"(a) : "l"(p));
    return a;
}

#define MMA16816F16(acc, a0, a1, a2, a3, b0, b1) \
    asm volatile("mma.sync.aligned.m16n8k16.row.col.f32.f16.f16.f32 " \
        "{%0,%1,%2,%3}, {%4,%5,%6,%7}, {%8,%9}, {%0,%1,%2,%3};" \
        : "+f"((acc)[0]), "+f"((acc)[1]), "+f"((acc)[2]), "+f"((acc)[3]) \
        : "r"(a0), "r"(a1), "r"(a2), "r"(a3), "r"(b0), "r"(b1))

#define LDSM4T(r0, r1, r2, r3, a) \
    asm volatile("ldmatrix.sync.aligned.m8n8.x4.trans.shared.b16 {%0,%1,%2,%3}, [%4];" \
        : "=r"(r0), "=r"(r1), "=r"(r2), "=r"(r3) : "r"(a))

#define LDSM4(r0, r1, r2, r3, a) \
    asm volatile("ldmatrix.sync.aligned.m8n8.x4.shared.b16 {%0,%1,%2,%3}, [%4];" \
        : "=r"(r0), "=r"(r1), "=r"(r2), "=r"(r3) : "r"(a))

__device__ __forceinline__ uint32_t pack_hi_f16x2(float a, float b) {
    uint32_t r;
    asm("cvt.rn.f16x2.f32 %0, %1, %2;" : "=r"(r) : "f"(b), "f"(a));
    return r;
}

// ---------------------------------------------------------------------------
// Kernel P: convert h and W to fp16 hi/lo.
// ---------------------------------------------------------------------------
__global__ void __launch_bounds__(256) prep_kernel(
    const float* __restrict__ h, const float* __restrict__ W)
{
    const int stride = gridDim.x * 256;
    // h: NN*FIN/4 float4 chunks
    for (int i = blockIdx.x * 256 + threadIdx.x; i < NN * FIN / 4; i += stride) {
        float4 v = ((const float4*)h)[i];
        __half hx = __float2half_rn(v.x), hy = __float2half_rn(v.y);
        __half hz = __float2half_rn(v.z), hw = __float2half_rn(v.w);
        uint32_t hi0 = (uint32_t)__half_as_ushort(hx) | ((uint32_t)__half_as_ushort(hy) << 16);
        uint32_t hi1 = (uint32_t)__half_as_ushort(hz) | ((uint32_t)__half_as_ushort(hw) << 16);
        uint32_t lo0 = pack_hi_f16x2(v.x - __half2float(hx), v.y - __half2float(hy));
        uint32_t lo1 = pack_hi_f16x2(v.z - __half2float(hz), v.w - __half2float(hw));
        ((uint2*)g_h16hi)[i] = make_uint2(hi0, hi1);
        ((uint2*)g_h16lo)[i] = make_uint2(lo0, lo1);
    }
    // W: NH*FIN*FO/4
    for (int i = blockIdx.x * 256 + threadIdx.x; i < NH * FIN * FO / 4; i += stride) {
        float4 v = ((const float4*)W)[i];
        __half hx = __float2half_rn(v.x), hy = __float2half_rn(v.y);
        __half hz = __float2half_rn(v.z), hw = __float2half_rn(v.w);
        uint32_t hi0 = (uint32_t)__half_as_ushort(hx) | ((uint32_t)__half_as_ushort(hy) << 16);
        uint32_t hi1 = (uint32_t)__half_as_ushort(hz) | ((uint32_t)__half_as_ushort(hw) << 16);
        uint32_t lo0 = pack_hi_f16x2(v.x - __half2float(hx), v.y - __half2float(hy));
        uint32_t lo1 = pack_hi_f16x2(v.z - __half2float(hz), v.w - __half2float(hw));
        ((uint2*)g_w16hi)[i] = make_uint2(hi0, hi1);
        ((uint2*)g_w16lo)[i] = make_uint2(lo0, lo1);
    }
}

// ---------------------------------------------------------------------------
// Kernel A: Wh = h @ W + bW via fp16 HMMA hi/lo split (fp32-accurate).
// CTA = 128 i-rows x 1 head, 256 threads (8 warps x 16 rows). K chunks of 64.
// Epilogue: +bW, store fp16 Wh, fused el/er (log2e-scaled).
// ---------------------------------------------------------------------------
#define ASTRIDE 72
#define WH_SMEM (128 * ASTRIDE * 2 * 2 + 64 * ASTRIDE * 2 * 2)  /* Ah+Al+Bh+Bl */

__global__ void __launch_bounds__(256) wh_mma_kernel(
    const float* __restrict__ bW, const float* __restrict__ a_l,
    const float* __restrict__ a_r, const float* __restrict__ bA)
{
    extern __shared__ __align__(16) unsigned short sm[];
    unsigned short* Ah = sm;                       // 128 x ASTRIDE
    unsigned short* Al = Ah + 128 * ASTRIDE;
    unsigned short* Bh = Al + 128 * ASTRIDE;       // 64 x ASTRIDE
    unsigned short* Bl = Bh + 64 * ASTRIDE;

    const int t    = threadIdx.x;
    const int warp = t >> 5;
    const int lane = t & 31;
    const int i0   = blockIdx.x * 128;
    const int hh   = blockIdx.y;

    const uint32_t ahB = smem_u32(Ah), alB = smem_u32(Al);
    const uint32_t bhB = smem_u32(Bh), blB = smem_u32(Bl);

    float acc[8][4];
#pragma unroll
    for (int n = 0; n < 8; n++)
#pragma unroll
        for (int j = 0; j < 4; j++) acc[n][j] = 0.f;

    // A-load indices: 1024 uint4 over 256 threads -> 4 each
    const int ar0 = t >> 1;                // rows t/2 pattern: id = t + 256*it
    (void)ar0;
    // ldsm addresses
    const uint32_t aRow = (uint32_t)(16 * warp + (lane & 15)) * (ASTRIDE * 2) + ((lane & 16) ? 16 : 0);
    const uint32_t bRow = (uint32_t)(lane & 15) * (ASTRIDE * 2) + ((lane & 16) ? 16 : 0);

    for (int ch = 0; ch < FIN / 64; ch++) {
        const int kc = ch * 64;
        __syncthreads();
        // load A chunk: rows 128, 64 k (8 uint4/row) -> 1024 uint4 per array
#pragma unroll
        for (int it = 0; it < 4; it++) {
            int id = t + 256 * it;
            int r = id >> 3, c = id & 7;
            size_t src = (size_t)(i0 + r) * FIN + kc + c * 8;
            *(uint4*)&Ah[r * ASTRIDE + c * 8] = *(const uint4*)(g_h16hi + src);
            *(uint4*)&Al[r * ASTRIDE + c * 8] = *(const uint4*)(g_h16lo + src);
        }
        // load B chunk: rows 64 k, 64 n -> 512 uint4 per array
#pragma unroll
        for (int it = 0; it < 2; it++) {
            int id = t + 256 * it;
            int r = id >> 3, c = id & 7;
            size_t src = ((size_t)hh * FIN + kc + r) * FO + c * 8;
            *(uint4*)&Bh[r * ASTRIDE + c * 8] = *(const uint4*)(g_w16hi + src);
            *(uint4*)&Bl[r * ASTRIDE + c * 8] = *(const uint4*)(g_w16lo + src);
        }
        __syncthreads();

#pragma unroll
        for (int kt = 0; kt < 4; kt++) {
            uint32_t ah0, ah1, ah2, ah3, al0, al1, al2, al3;
            LDSM4(ah0, ah1, ah2, ah3, ahB + aRow + kt * 32);
            LDSM4(al0, al1, al2, al3, alB + aRow + kt * 32);
            const uint32_t kOff = (uint32_t)(16 * kt) * (ASTRIDE * 2) + bRow;
#pragma unroll
            for (int ntp = 0; ntp < 4; ntp++) {
                uint32_t bh0, bh1, bh2, bh3, bl0, bl1, bl2, bl3;
                LDSM4T(bh0, bh1, bh2, bh3, bhB + kOff + 32 * ntp);
                LDSM4T(bl0, bl1, bl2, bl3, blB + kOff + 32 * ntp);
                MMA16816F16(acc[2 * ntp],     ah0, ah1, ah2, ah3, bh0, bh1);
                MMA16816F16(acc[2 * ntp],     al0, al1, al2, al3, bh0, bh1);
                MMA16816F16(acc[2 * ntp],     ah0, ah1, ah2, ah3, bl0, bl1);
                MMA16816F16(acc[2 * ntp + 1], ah0, ah1, ah2, ah3, bh2, bh3);
                MMA16816F16(acc[2 * ntp + 1], al0, al1, al2, al3, bh2, bh3);
                MMA16816F16(acc[2 * ntp + 1], ah0, ah1, ah2, ah3, bl2, bl3);
            }
        }
    }

    // ---- epilogue: bias, store fp16 Wh, fused el/er ----
    const int q  = lane >> 2;
    const int c2 = 2 * (lane & 3);
    const int r0 = i0 + 16 * warp + q;
    const int r1 = r0 + 8;

    float dl0 = 0.f, dr0 = 0.f, dl1 = 0.f, dr1 = 0.f;
#pragma unroll
    for (int nt = 0; nt < 8; nt++) {
        int col = 8 * nt + c2;
        float2 bw = *(const float2*)(bW + hh * FO + col);
        float2 al = *(const float2*)(a_l + hh * FO + col);
        float2 ar = *(const float2*)(a_r + hh * FO + col);
        float v00 = acc[nt][0] + bw.x, v01 = acc[nt][1] + bw.y;
        float v10 = acc[nt][2] + bw.x, v11 = acc[nt][3] + bw.y;
        *(uint32_t*)(g_wh16 + ((size_t)hh * NN + r0) * FO + col) = pack_hi_f16x2(v00, v01);
        *(uint32_t*)(g_wh16 + ((size_t)hh * NN + r1) * FO + col) = pack_hi_f16x2(v10, v11);
        dl0 += v00 * al.x + v01 * al.y;
        dr0 += v00 * ar.x + v01 * ar.y;
        dl1 += v10 * al.x + v11 * al.y;
        dr1 += v10 * ar.x + v11 * ar.y;
    }
#pragma unroll
    for (int off = 1; off < 4; off <<= 1) {
        dl0 += __shfl_xor_sync(0xffffffffu, dl0, off);
        dr0 += __shfl_xor_sync(0xffffffffu, dr0, off);
        dl1 += __shfl_xor_sync(0xffffffffu, dl1, off);
        dr1 += __shfl_xor_sync(0xffffffffu, dr1, off);
    }
    if ((lane & 3) == 0) {
        float ba = bA[hh];
        g_el[hh * NN + r0] = (dl0 + ba) * LOG2E;
        g_er[hh * NN + r0] = dr0 * LOG2E;
        g_el[hh * NN + r1] = (dl1 + ba) * LOG2E;
        g_er[hh * NN + r1] = dr1 * LOG2E;
    }
}

// ---------------------------------------------------------------------------
// Kernel A2: mask -> bitmap
// ---------------------------------------------------------------------------
__global__ void __launch_bounds__(256) mask_bits_kernel(const int* __restrict__ mask)
{
    int gw   = (blockIdx.x * 256 + threadIdx.x) >> 5;
    int lane = threadIdx.x & 31;
    int row  = gw >> 7;
    int wd   = gw & (NWORD - 1);
    int m = mask[(size_t)row * NN + wd * 32 + lane];
    uint32_t b = __ballot_sync(0xffffffffu, m > 0);
    if (lane == 0) g_bits[gw] = b;
}

// ---------------------------------------------------------------------------
// Kernel B: er_max[h]
// ---------------------------------------------------------------------------
__global__ void __launch_bounds__(256) ermax_kernel()
{
    __shared__ float red[256];
    int hh = blockIdx.x;
    float m = -1e30f;
    for (int i = threadIdx.x; i < NN; i += 256)
        m = fmaxf(m, g_er[hh * NN + i]);
    red[threadIdx.x] = m;
    __syncthreads();
    for (int s = 128; s > 0; s >>= 1) {
        if (threadIdx.x < s)
            red[threadIdx.x] = fmaxf(red[threadIdx.x], red[threadIdx.x + s]);
        __syncthreads();
    }
    if (threadIdx.x == 0) g_ermax[hh] = red[0];
}

// ---------------------------------------------------------------------------
// Kernel C: fp16 HMMA flash-GAT.
// Score refactor: with el' = el - c and d = (ALPHA-1)*c,
//   lrelu(el+er) - c = max(x', ALPHA*x' + d),  x' = el' + er.
// Denominator: one MMA per kt against a constant all-ones B fragment
// (every output column equals the row sum; read col pair directly).
// ---------------------------------------------------------------------------
__device__ __forceinline__ float elu(float v) {
    return v > 0.f ? v : (__expf(v) - 1.f);
}

__device__ __forceinline__ uint32_t pscore2(float2 ed, float2 er, uint32_t b2) {
    float x0 = ed.x + er.x;
    float a0 = fmaxf(x0, fmaf(ALPHA, x0, ed.y));
    float x1 = ed.x + er.y;
    float a1 = fmaxf(x1, fmaf(ALPHA, x1, ed.y));
    uint32_t ph, pe;
    asm("cvt.rn.f16x2.f32 %0, %1, %2;" : "=r"(ph) : "f"(a1), "f"(a0));
    asm("ex2.approx.f16x2 %0, %1;" : "=r"(pe) : "r"(ph));
    uint32_t msk = ((b2 & 1u) ? 0x0000FFFFu : 0u) | ((b2 & 2u) ? 0xFFFF0000u : 0u);
    return pe & msk;
}

#define BSTRIDE 72

__global__ void __launch_bounds__(256, 2) gat_attn_mma_kernel(float* __restrict__ out)
{
    __shared__ __align__(16) unsigned short Bs[2][64 * BSTRIDE];
    __shared__ float2 els2[128];

    const int t    = threadIdx.x;
    const int warp = t >> 5;
    const int lane = t & 31;
    const int i0   = blockIdx.x * 128;
    const int hh   = blockIdx.y;

    if (t < 128) {
        float e = g_el[hh * NN + i0 + t];
        float z = e + g_ermax[hh];
        float c = fmaxf(z, ALPHA * z);
        els2[t] = make_float2(e - c, (ALPHA - 1.f) * c);
    }

    const int q  = lane >> 2;
    const int c2 = 2 * (lane & 3);
    const int rw0 = 16 * warp + q;

    const float* erb = g_er + hh * NN + c2;
    const unsigned short* gwh = g_wh16 + (size_t)hh * NN * FO;
    const uint32_t* bitrow = g_bits + (size_t)(i0 + 16 * warp + (lane >> 1)) * NWORD + (lane & 1);

    const uint32_t bBase = smem_u32(Bs);
    const uint32_t lrowOff = (uint32_t)(lane & 15) * (BSTRIDE * 2) + ((lane & 16) ? 16 : 0);

    const int lk0 = t >> 3, lc0 = t & 7;
    const int lk1 = (t + 256) >> 3, lc1 = t & 7;

    float acc[8][4];
#pragma unroll
    for (int n = 0; n < 8; n++)
#pragma unroll
        for (int j = 0; j < 4; j++) acc[n][j] = 0.f;
    float accd[4] = {0.f, 0.f, 0.f, 0.f};
    const uint32_t ONES = 0x3C003C00u;

    // preload tile 0
    {
        uint4 va = *(const uint4*)(gwh + (size_t)lk0 * FO + lc0 * 8);
        uint4 vb = *(const uint4*)(gwh + (size_t)lk1 * FO + lc1 * 8);
        *(uint4*)&Bs[0][lk0 * BSTRIDE + lc0 * 8] = va;
        *(uint4*)&Bs[0][lk1 * BSTRIDE + lc1 * 8] = vb;
    }
    __syncthreads();

    const float2 ec0 = els2[rw0];
    const float2 ec1 = els2[rw0 + 8];

    for (int tile = 0; tile < NN / 64; tile++) {
        const int j0 = tile * 64;
        const int cur = tile & 1;

        uint32_t bv = bitrow[(uint32_t)(j0 >> 5)];
        uint32_t w00 = __shfl_sync(0xffffffffu, bv, 2 * q);
        uint32_t w01 = __shfl_sync(0xffffffffu, bv, 2 * q + 1);
        uint32_t w10 = __shfl_sync(0xffffffffu, bv, 2 * q + 16);
        uint32_t w11 = __shfl_sync(0xffffffffu, bv, 2 * q + 17);

        uint4 na, nb;
        if (tile < NN / 64 - 1) {
            const unsigned short* src = gwh + (size_t)(j0 + 64) * FO;
            na = *(const uint4*)(src + (size_t)lk0 * FO + lc0 * 8);
            nb = *(const uint4*)(src + (size_t)lk1 * FO + lc1 * 8);
        }

        const uint32_t bufOff = bBase + cur * (64 * BSTRIDE * 2) + lrowOff;

#pragma unroll
        for (int kt = 0; kt < 4; kt++) {
            const int jb = j0 + 16 * kt;
            float2 e0 = *(const float2*)(erb + jb);
            float2 e1 = *(const float2*)(erb + jb + 8);

            uint32_t wr0 = (kt < 2) ? w00 : w01;
            uint32_t wr1 = (kt < 2) ? w10 : w11;
            const int sb = (kt & 1) * 16;
            uint32_t v0 = wr0 >> (sb + c2);
            uint32_t v1 = wr1 >> (sb + c2);

            uint32_t a0 = pscore2(ec0, e0, v0 & 3u);
            uint32_t a1 = pscore2(ec1, e0, v1 & 3u);
            uint32_t a2 = pscore2(ec0, e1, (v0 >> 8) & 3u);
            uint32_t a3 = pscore2(ec1, e1, (v1 >> 8) & 3u);

            const uint32_t kOff = bufOff + (uint32_t)(16 * kt) * (BSTRIDE * 2);
#pragma unroll
            for (int ntp = 0; ntp < 4; ntp++) {
                uint32_t b0, b1, b2, b3;
                LDSM4T(b0, b1, b2, b3, kOff + 32 * ntp);
                MMA16816F16(acc[2 * ntp],     a0, a1, a2, a3, b0, b1);
                MMA16816F16(acc[2 * ntp + 1], a0, a1, a2, a3, b2, b3);
            }
            MMA16816F16(accd, a0, a1, a2, a3, ONES, ONES);
        }

        if (tile < NN / 64 - 1) {
            unsigned short* dst = &Bs[cur ^ 1][0];
            *(uint4*)&dst[lk0 * BSTRIDE + lc0 * 8] = na;
            *(uint4*)&dst[lk1 * BSTRIDE + lc1 * 8] = nb;
        }
        __syncthreads();
    }

    const float inv0 = 1.f / accd[0];
    const float inv1 = 1.f / accd[2];

    float* ob0 = out + (size_t)(i0 + rw0) * OUTW + hh * FO + c2;
    float* ob1 = ob0 + (size_t)8 * OUTW;
#pragma unroll
    for (int nt = 0; nt < 8; nt++) {
        float2 v0 = make_float2(elu(acc[nt][0] * inv0), elu(acc[nt][1] * inv0));
        float2 v1 = make_float2(elu(acc[nt][2] * inv1), elu(acc[nt][3] * inv1));
        *(float2*)(ob0 + 8 * nt) = v0;
        *(float2*)(ob1 + 8 * nt) = v1;
    }
}

// ---------------------------------------------------------------------------
extern "C" void kernel_launch(void* const* d_in, const int* in_sizes, int n_in,
                              void* d_out, int out_size)
{
    const float* h    = (const float*)d_in[0];  // [N, FIN]
    const int*   mask = (const int*)  d_in[1];  // [N, N]
    const float* W    = (const float*)d_in[2];  // [H, FIN, FO]
    const float* bW   = (const float*)d_in[3];  // [H, FO]
    const float* a_l  = (const float*)d_in[4];  // [H, FO]
    const float* a_r  = (const float*)d_in[5];  // [H, FO]
    const float* bA   = (const float*)d_in[6];  // [H]
    float* out = (float*)d_out;                 // [N, H*FO]

    cudaFuncSetAttribute(wh_mma_kernel,
                         cudaFuncAttributeMaxDynamicSharedMemorySize, WH_SMEM);

    prep_kernel<<<1024, 256>>>(h, W);
    wh_mma_kernel<<<dim3(NN / 128, NH), 256, WH_SMEM>>>(bW, a_l, a_r, bA);
    mask_bits_kernel<<<NN * NWORD / 8, 256>>>(mask);
    ermax_kernel<<<NH, 256>>>();
    gat_attn_mma_kernel<<<dim3(NN / 128, NH), 256>>>(out);
}